// round 1
// baseline (speedup 1.0000x reference)
#include <cuda_runtime.h>
#include <math.h>

#define Bb 16
#define T 2048
#define Cc 12
#define H 256
#define DEPTH 5
#define OUTD 10
#define DS 16
#define DC 4
#define DI 512
#define DR 16
#define M_TOT (Bb*T)          // 32768
#define DBLW (DR + 2*DS)      // 48

// ---------------- scratch (device globals; no allocation allowed) ----------
__device__ float  g_h   [M_TOT * H];        // residual stream
__device__ float  g_xz  [M_TOT * 2 * DI];   // in_proj out (xin | z)
__device__ float  g_xc  [M_TOT * DI];       // conv+silu out
__device__ float  g_dbl [M_TOT * DBLW];     // x_proj out (dtr|B|C)
__device__ float4 g_P   [M_TOT * DI];       // packed {dt, dt*xc, Dp*xc, silu(z)}
__device__ float  g_y   [M_TOT * DI];       // scan output
__device__ float  g_out [M_TOT * H];        // out_proj out
__device__ float  g_Wc  [H * Cc * 7];       // combined front conv weights
__device__ float  g_part[16 * Bb * H];      // mean partials (T/128 chunks)
__device__ float  g_hmean[Bb * H];

// ---------------- front conv: fold 3/5/7-tap convs into one 7-tap ----------
__global__ void prep_front(const float* __restrict__ w3, const float* __restrict__ w5,
                           const float* __restrict__ w7) {
    int i = blockIdx.x * blockDim.x + threadIdx.x;
    if (i >= H * Cc * 7) return;
    int j = i % 7, hc = i / 7;
    float v = w7[hc * 7 + j];
    if (j >= 1 && j <= 5) v += w5[hc * 5 + (j - 1)];
    if (j >= 2 && j <= 4) v += w3[hc * 3 + (j - 2)];
    g_Wc[i] = v * (1.0f / 3.0f);
}

__global__ void front_conv(const float* __restrict__ x, const float* __restrict__ b3,
                           const float* __restrict__ b5, const float* __restrict__ b7) {
    int m = blockIdx.x;
    int b = m / T, t = m % T;
    __shared__ float sx[7 * Cc];
    int tid = threadIdx.x;
    if (tid < 7 * Cc) {
        int j = tid / Cc, c = tid % Cc;
        int tt = t + j - 3;
        sx[j * Cc + c] = (tt >= 0 && tt < T) ? x[((size_t)(b * T + tt)) * Cc + c] : 0.f;
    }
    __syncthreads();
    int hh = tid;  // 256 threads
    const float* W = &g_Wc[hh * Cc * 7];
    float acc = 0.f;
#pragma unroll
    for (int c = 0; c < Cc; c++)
#pragma unroll
        for (int j = 0; j < 7; j++)
            acc += sx[j * Cc + c] * W[c * 7 + j];
    acc += (b3[hh] + b5[hh] + b7[hh]) * (1.f / 3.f);
    g_h[(size_t)m * H + hh] = acc;
}

// ---------------- generic NT SGEMM: C[m,n] = sum_k A[m,k]*B[n,k] ------------
// 64x64 tile, BK=16, 256 threads, 4x4 per thread. M%64==0, K%16==0 assumed.
__global__ void __launch_bounds__(256) sgemm_nt(
    const float* __restrict__ A, const float* __restrict__ Bm,
    float* __restrict__ C, int M, int N, int K) {
    __shared__ float As[16][68];
    __shared__ float Bs[16][68];
    int tid = threadIdx.x;
    int tx = tid & 15, ty = tid >> 4;
    int m0 = blockIdx.y * 64, n0 = blockIdx.x * 64;
    int lrow = tid >> 2;           // 0..63
    int lk = (tid & 3) * 4;        // 0,4,8,12
    float acc[4][4] = {};
    for (int k0 = 0; k0 < K; k0 += 16) {
        float4 av = *(const float4*)(A + (size_t)(m0 + lrow) * K + k0 + lk);
        As[lk + 0][lrow] = av.x; As[lk + 1][lrow] = av.y;
        As[lk + 2][lrow] = av.z; As[lk + 3][lrow] = av.w;
        float4 bv = make_float4(0.f, 0.f, 0.f, 0.f);
        if (n0 + lrow < N) bv = *(const float4*)(Bm + (size_t)(n0 + lrow) * K + k0 + lk);
        Bs[lk + 0][lrow] = bv.x; Bs[lk + 1][lrow] = bv.y;
        Bs[lk + 2][lrow] = bv.z; Bs[lk + 3][lrow] = bv.w;
        __syncthreads();
#pragma unroll
        for (int kk = 0; kk < 16; kk++) {
            float4 a = *(const float4*)&As[kk][ty * 4];
            float4 bq = *(const float4*)&Bs[kk][tx * 4];
            acc[0][0] += a.x * bq.x; acc[0][1] += a.x * bq.y; acc[0][2] += a.x * bq.z; acc[0][3] += a.x * bq.w;
            acc[1][0] += a.y * bq.x; acc[1][1] += a.y * bq.y; acc[1][2] += a.y * bq.z; acc[1][3] += a.y * bq.w;
            acc[2][0] += a.z * bq.x; acc[2][1] += a.z * bq.y; acc[2][2] += a.z * bq.z; acc[2][3] += a.z * bq.w;
            acc[3][0] += a.w * bq.x; acc[3][1] += a.w * bq.y; acc[3][2] += a.w * bq.z; acc[3][3] += a.w * bq.w;
        }
        __syncthreads();
    }
#pragma unroll
    for (int i = 0; i < 4; i++) {
        size_t mrow = m0 + ty * 4 + i;
#pragma unroll
        for (int j = 0; j < 4; j++) {
            int n = n0 + tx * 4 + j;
            if (n < N) C[mrow * N + n] = acc[i][j];
        }
    }
}

// ---------------- causal depthwise conv (DC=4) + silu ----------------------
__global__ void dwconv(const float* __restrict__ cw, const float* __restrict__ cb) {
    int idx = blockIdx.x * blockDim.x + threadIdx.x;   // over M_TOT*DI
    int d = idx & (DI - 1);
    int m = idx >> 9;
    int t = m & (T - 1);
    float acc = cb[d];
#pragma unroll
    for (int j = 0; j < DC; j++) {
        int tt = t + j - (DC - 1);
        if (tt >= 0)
            acc += g_xz[(size_t)(m + j - (DC - 1)) * (2 * DI) + d] * cw[d * DC + j];
    }
    float s = acc / (1.f + __expf(-acc));
    g_xc[(size_t)m * DI + d] = s;
}

// ---------------- dt proj + softplus + packing -----------------------------
__global__ void dt_pack(const float* __restrict__ dtw, const float* __restrict__ dtb,
                        const float* __restrict__ Dp) {
    int m = blockIdx.x;
    int d = threadIdx.x;   // 512
    __shared__ float sdtr[DR];
    if (d < DR) sdtr[d] = g_dbl[(size_t)m * DBLW + d];
    __syncthreads();
    float acc = dtb[d];
    const float4* w = (const float4*)(dtw + d * DR);
#pragma unroll
    for (int r4 = 0; r4 < 4; r4++) {
        float4 wv = w[r4];
        acc += sdtr[r4 * 4 + 0] * wv.x + sdtr[r4 * 4 + 1] * wv.y +
               sdtr[r4 * 4 + 2] * wv.z + sdtr[r4 * 4 + 3] * wv.w;
    }
    float dt = fmaxf(acc, 0.f) + log1pf(__expf(-fabsf(acc)));   // softplus
    float xc = g_xc[(size_t)m * DI + d];
    float z = g_xz[(size_t)m * 2 * DI + DI + d];
    float sz = z / (1.f + __expf(-z));
    g_P[(size_t)m * DI + d] = make_float4(dt, dt * xc, Dp[d] * xc, sz);
}

// ---------------- selective scan: 4 lanes per (b,d), 4 states per lane -----
__global__ void __launch_bounds__(128) scan_kernel(const float* __restrict__ A_log) {
    int b = blockIdx.y;
    int sp = threadIdx.x & 3;
    int d = blockIdx.x * 32 + (threadIdx.x >> 2);
    float An[4], h[4] = {0.f, 0.f, 0.f, 0.f};
#pragma unroll
    for (int i = 0; i < 4; i++) An[i] = -__expf(A_log[d * DS + sp * 4 + i]);
    const float4* Pp = &g_P[(size_t)b * T * DI + d];
    const float* dblb = g_dbl + (size_t)b * T * DBLW;
    float* yp = g_y + (size_t)b * T * DI + d;
    for (int t = 0; t < T; t++) {
        float4 p = Pp[(size_t)t * DI];
        float4 Bv = *(const float4*)(dblb + (size_t)t * DBLW + DR + sp * 4);
        float4 Cv = *(const float4*)(dblb + (size_t)t * DBLW + DR + DS + sp * 4);
        float y;
        h[0] = h[0] * __expf(p.x * An[0]) + p.y * Bv.x;  y  = h[0] * Cv.x;
        h[1] = h[1] * __expf(p.x * An[1]) + p.y * Bv.y;  y += h[1] * Cv.y;
        h[2] = h[2] * __expf(p.x * An[2]) + p.y * Bv.z;  y += h[2] * Cv.z;
        h[3] = h[3] * __expf(p.x * An[3]) + p.y * Bv.w;  y += h[3] * Cv.w;
        y += __shfl_xor_sync(0xffffffffu, y, 1);
        y += __shfl_xor_sync(0xffffffffu, y, 2);
        if (sp == 0) yp[(size_t)t * DI] = (y + p.z) * p.w;
    }
}

// ---------------- residual add + layernorm ---------------------------------
__global__ void resid_ln(const float* __restrict__ g, const float* __restrict__ bb) {
    int m = blockIdx.x;
    int hh = threadIdx.x;  // 256
    float v = g_h[(size_t)m * H + hh] + g_out[(size_t)m * H + hh];
    __shared__ float red[8];
    __shared__ float smean, srstd;
    float s = v;
#pragma unroll
    for (int o = 16; o > 0; o >>= 1) s += __shfl_xor_sync(~0u, s, o);
    if ((hh & 31) == 0) red[hh >> 5] = s;
    __syncthreads();
    if (hh == 0) {
        float tot = 0;
#pragma unroll
        for (int i = 0; i < 8; i++) tot += red[i];
        smean = tot * (1.f / H);
    }
    __syncthreads();
    float dv = v - smean;
    float q = dv * dv;
#pragma unroll
    for (int o = 16; o > 0; o >>= 1) q += __shfl_xor_sync(~0u, q, o);
    if ((hh & 31) == 0) red[hh >> 5] = q;
    __syncthreads();
    if (hh == 0) {
        float tot = 0;
#pragma unroll
        for (int i = 0; i < 8; i++) tot += red[i];
        srstd = rsqrtf(tot * (1.f / H) + 1e-5f);
    }
    __syncthreads();
    g_h[(size_t)m * H + hh] = dv * srstd * g[hh] + bb[hh];
}

// ---------------- mean over T (deterministic two-stage) + final proj -------
__global__ void mean_part() {
    int b = blockIdx.y;
    int chunk = blockIdx.x;   // 16 chunks of 128 timesteps
    int hh = threadIdx.x;     // 256
    float acc = 0.f;
    for (int tt = 0; tt < 128; tt++) {
        int t = chunk * 128 + tt;
        acc += g_h[((size_t)(b * T + t)) * H + hh];
    }
    g_part[(size_t)chunk * Bb * H + b * H + hh] = acc;
}

__global__ void mean_comb() {
    int i = blockIdx.x * blockDim.x + threadIdx.x;
    if (i >= Bb * H) return;
    float a = 0.f;
#pragma unroll
    for (int c = 0; c < 16; c++) a += g_part[(size_t)c * Bb * H + i];
    g_hmean[i] = a * (1.f / T);
}

__global__ void final_proj(const float* __restrict__ ow, const float* __restrict__ ob,
                           float* __restrict__ out) {
    int i = threadIdx.x;
    if (i >= Bb * OUTD) return;
    int b = i / OUTD, o = i % OUTD;
    float acc = 0.f;
    for (int hh = 0; hh < H; hh++) acc += g_hmean[b * H + hh] * ow[o * H + hh];
    out[b * OUTD + o] = acc + ob[o];
}

// ---------------- launch ----------------------------------------------------
extern "C" void kernel_launch(void* const* d_in, const int* in_sizes, int n_in,
                              void* d_out, int out_size) {
    const float* x     = (const float*)d_in[0];
    const float* w3    = (const float*)d_in[1];
    const float* b3    = (const float*)d_in[2];
    const float* w5    = (const float*)d_in[3];
    const float* b5    = (const float*)d_in[4];
    const float* w7    = (const float*)d_in[5];
    const float* b7    = (const float*)d_in[6];
    const float* ipw   = (const float*)d_in[7];
    const float* cw    = (const float*)d_in[8];
    const float* cb    = (const float*)d_in[9];
    const float* xpw   = (const float*)d_in[10];
    const float* dtw   = (const float*)d_in[11];
    const float* dtb   = (const float*)d_in[12];
    const float* A_log = (const float*)d_in[13];
    const float* Dp    = (const float*)d_in[14];
    const float* opw   = (const float*)d_in[15];
    const float* ln_g  = (const float*)d_in[16];
    const float* ln_b  = (const float*)d_in[17];
    const float* ow    = (const float*)d_in[18];
    const float* ob    = (const float*)d_in[19];

    float *ph, *pxz, *pxc, *pdbl, *py, *pout;
    cudaGetSymbolAddress((void**)&ph,   g_h);
    cudaGetSymbolAddress((void**)&pxz,  g_xz);
    cudaGetSymbolAddress((void**)&pxc,  g_xc);
    cudaGetSymbolAddress((void**)&pdbl, g_dbl);
    cudaGetSymbolAddress((void**)&py,   g_y);
    cudaGetSymbolAddress((void**)&pout, g_out);

    prep_front<<<(H * Cc * 7 + 255) / 256, 256>>>(w3, w5, w7);
    front_conv<<<M_TOT, 256>>>(x, b3, b5, b7);

    for (int l = 0; l < DEPTH; l++) {
        // in_proj: [M, 1024] = h[M,256] x ipw[1024,256]^T
        sgemm_nt<<<dim3((2 * DI) / 64, M_TOT / 64), 256>>>(
            ph, ipw + (size_t)l * 2 * DI * H, pxz, M_TOT, 2 * DI, H);
        // depthwise causal conv + silu
        dwconv<<<(M_TOT * DI) / 256, 256>>>(cw + (size_t)l * DI * DC, cb + (size_t)l * DI);
        // x_proj: [M, 48] = xc[M,512] x xpw[48,512]^T
        sgemm_nt<<<dim3(1, M_TOT / 64), 256>>>(
            pxc, xpw + (size_t)l * DBLW * DI, pdbl, M_TOT, DBLW, DI);
        // dt proj + softplus + pack
        dt_pack<<<M_TOT, DI>>>(dtw + (size_t)l * DI * DR, dtb + (size_t)l * DI,
                               Dp + (size_t)l * DI);
        // selective scan
        scan_kernel<<<dim3(DI / 32, Bb), 128>>>(A_log + (size_t)l * DI * DS);
        // out_proj: [M, 256] = y[M,512] x opw[256,512]^T
        sgemm_nt<<<dim3(H / 64, M_TOT / 64), 256>>>(
            py, opw + (size_t)l * H * DI, pout, M_TOT, H, DI);
        // residual + layernorm
        resid_ln<<<M_TOT, H>>>(ln_g, ln_b);
    }

    mean_part<<<dim3(T / 128, Bb), H>>>();
    mean_comb<<<(Bb * H + 255) / 256, 256>>>();
    final_proj<<<1, 256>>>(ow, ob, (float*)d_out);
}

// round 2
// speedup vs baseline: 1.3196x; 1.3196x over previous
#include <cuda_runtime.h>
#include <cuda_bf16.h>
#include <math.h>
#include <stdint.h>

#define Bb 16
#define T 2048
#define Cc 12
#define H 256
#define DEPTH 5
#define OUTD 10
#define DS 16
#define DC 4
#define DI 512
#define DR 16
#define M_TOT (Bb*T)          // 32768
#define DBLW (DR + 2*DS)      // 48
#define XPW_PAD 64            // x_proj weight rows padded 48 -> 64

// ---------------- scratch (device globals; no allocation allowed) ----------
__device__ float  g_h   [M_TOT * H];        // residual stream (fp32)
__device__ float  g_xz  [M_TOT * 2 * DI];   // in_proj out (xin | z)
__device__ float  g_xc  [M_TOT * DI];       // conv+silu out (fp32)
__device__ float  g_dbl [M_TOT * DBLW];     // x_proj out (dtr|B|C)
__device__ float4 g_P   [M_TOT * DI];       // packed {dt, dt*xc, Dp*xc, silu(z)}
__device__ float  g_out [M_TOT * H];        // out_proj out
__device__ float  g_Wc  [H * Cc * 7];       // combined front conv weights
__device__ float  g_part[16 * Bb * H];
__device__ float  g_hmean[Bb * H];

// bf16 hi/lo activation mirrors (for tensor-core GEMMs)
__device__ __nv_bfloat16 g_hh [M_TOT * H],  g_hl [M_TOT * H];
__device__ __nv_bfloat16 g_xch[M_TOT * DI], g_xcl[M_TOT * DI];
__device__ __nv_bfloat16 g_yh [M_TOT * DI], g_yl [M_TOT * DI];

// bf16 hi/lo weights
__device__ __nv_bfloat16 g_ipw_h[DEPTH * 2 * DI * H],   g_ipw_l[DEPTH * 2 * DI * H];
__device__ __nv_bfloat16 g_xpw_h[DEPTH * XPW_PAD * DI], g_xpw_l[DEPTH * XPW_PAD * DI];
__device__ __nv_bfloat16 g_opw_h[DEPTH * H * DI],       g_opw_l[DEPTH * H * DI];

__device__ __forceinline__ void split2(float v, __nv_bfloat16& h, __nv_bfloat16& l) {
    h = __float2bfloat16_rn(v);
    l = __float2bfloat16_rn(v - __bfloat162float(h));
}

// ---------------- weight conversion -----------------------------------------
__global__ void cvt_split(const float* __restrict__ in, __nv_bfloat16* __restrict__ hi,
                          __nv_bfloat16* __restrict__ lo, int n) {
    int i = blockIdx.x * 256 + threadIdx.x;
    if (i >= n) return;
    split2(in[i], hi[i], lo[i]);
}

__global__ void cvt_xpw(const float* __restrict__ in) {
    int i = blockIdx.x * 256 + threadIdx.x;
    if (i >= DEPTH * XPW_PAD * DI) return;
    int k = i % DI;
    int r = (i / DI) % XPW_PAD;
    int l = i / (DI * XPW_PAD);
    float v = (r < DBLW) ? in[((size_t)l * DBLW + r) * DI + k] : 0.f;
    split2(v, g_xpw_h[i], g_xpw_l[i]);
}

// ---------------- front conv -------------------------------------------------
__global__ void prep_front(const float* __restrict__ w3, const float* __restrict__ w5,
                           const float* __restrict__ w7) {
    int i = blockIdx.x * blockDim.x + threadIdx.x;
    if (i >= H * Cc * 7) return;
    int j = i % 7, hc = i / 7;
    float v = w7[hc * 7 + j];
    if (j >= 1 && j <= 5) v += w5[hc * 5 + (j - 1)];
    if (j >= 2 && j <= 4) v += w3[hc * 3 + (j - 2)];
    g_Wc[i] = v * (1.0f / 3.0f);
}

__global__ void front_conv(const float* __restrict__ x, const float* __restrict__ b3,
                           const float* __restrict__ b5, const float* __restrict__ b7) {
    int m = blockIdx.x;
    int b = m / T, t = m % T;
    __shared__ float sx[7 * Cc];
    int tid = threadIdx.x;
    if (tid < 7 * Cc) {
        int j = tid / Cc, c = tid % Cc;
        int tt = t + j - 3;
        sx[j * Cc + c] = (tt >= 0 && tt < T) ? x[((size_t)(b * T + tt)) * Cc + c] : 0.f;
    }
    __syncthreads();
    int hh = tid;
    const float* W = &g_Wc[hh * Cc * 7];
    float acc = 0.f;
#pragma unroll
    for (int c = 0; c < Cc; c++)
#pragma unroll
        for (int j = 0; j < 7; j++)
            acc += sx[j * Cc + c] * W[c * 7 + j];
    acc += (b3[hh] + b5[hh] + b7[hh]) * (1.f / 3.f);
    size_t idx = (size_t)m * H + hh;
    g_h[idx] = acc;
    split2(acc, g_hh[idx], g_hl[idx]);
}

// ---------------- tensor-core GEMM: C[m,n] = sum_k A[m,k]*B[n,k] -------------
// 3x bf16 split: C ~= Ah*Bh + Ah*Bl + Al*Bh.  BM=128, BK=16, 256 threads.
// Smem XOR-swizzled for conflict-free ldmatrix; cp.async double buffered.
#define MMA_B16(c, a, b) asm volatile( \
    "mma.sync.aligned.m16n8k16.row.col.f32.bf16.bf16.f32 " \
    "{%0,%1,%2,%3},{%4,%5,%6,%7},{%8,%9},{%0,%1,%2,%3};" \
    : "+f"(c[0]), "+f"(c[1]), "+f"(c[2]), "+f"(c[3]) \
    : "r"(a[0]), "r"(a[1]), "r"(a[2]), "r"(a[3]), "r"(b[0]), "r"(b[1]))

#define LDSM4(r, p) asm volatile( \
    "ldmatrix.sync.aligned.m8n8.x4.shared.b16 {%0,%1,%2,%3}, [%4];" \
    : "=r"(r[0]), "=r"(r[1]), "=r"(r[2]), "=r"(r[3]) : "r"(p))

// swizzled halfword offset within one [rows][16] tile
__device__ __forceinline__ int swz(int r, int kc) {  // kc in {0,8}
    return r * 16 + (((kc >> 3) ^ ((r >> 2) & 1)) << 3);
}

template<int BN_>
__global__ void __launch_bounds__(256) mma_gemm(
    const __nv_bfloat16* __restrict__ Ahg, const __nv_bfloat16* __restrict__ Alg,
    const __nv_bfloat16* __restrict__ Bhg, const __nv_bfloat16* __restrict__ Blg,
    float* __restrict__ C, int N, int K) {
    constexpr int BM = 128;
    constexpr int WGM = (BN_ == 128) ? 2 : 4;
    constexpr int WGN = 8 / WGM;
    constexpr int MI = BM / (WGM * 16);
    constexpr int NI = BN_ / (WGN * 8);

    __shared__ __nv_bfloat16 sAh[2][BM * 16], sAl[2][BM * 16];
    __shared__ __nv_bfloat16 sBh[2][BN_ * 16], sBl[2][BN_ * 16];

    int tid = threadIdx.x;
    int wid = tid >> 5, lane = tid & 31;
    int warp_m = wid % WGM, warp_n = wid / WGM;
    int m0 = blockIdx.y * BM, n0 = blockIdx.x * BN_;
    int KT = K / 16;

    int arow = tid >> 1, acol = (tid & 1) * 8;
    int aoff = swz(arow, acol);

    auto load_stage = [&](int kt, int buf) {
        int k0 = kt * 16;
        const __nv_bfloat16* gah = Ahg + (size_t)(m0 + arow) * K + k0 + acol;
        const __nv_bfloat16* gal = Alg + (size_t)(m0 + arow) * K + k0 + acol;
        uint32_t dah = (uint32_t)__cvta_generic_to_shared(&sAh[buf][aoff]);
        uint32_t dal = (uint32_t)__cvta_generic_to_shared(&sAl[buf][aoff]);
        asm volatile("cp.async.ca.shared.global [%0], [%1], 16;" :: "r"(dah), "l"(gah));
        asm volatile("cp.async.ca.shared.global [%0], [%1], 16;" :: "r"(dal), "l"(gal));
        if (BN_ == 128 || tid < 128) {
            const __nv_bfloat16* gbh = Bhg + (size_t)(n0 + arow) * K + k0 + acol;
            const __nv_bfloat16* gbl = Blg + (size_t)(n0 + arow) * K + k0 + acol;
            uint32_t dbh = (uint32_t)__cvta_generic_to_shared(&sBh[buf][aoff]);
            uint32_t dbl_ = (uint32_t)__cvta_generic_to_shared(&sBl[buf][aoff]);
            asm volatile("cp.async.ca.shared.global [%0], [%1], 16;" :: "r"(dbh), "l"(gbh));
            asm volatile("cp.async.ca.shared.global [%0], [%1], 16;" :: "r"(dbl_), "l"(gbl));
        }
        asm volatile("cp.async.commit_group;");
    };

    float acc[MI][NI][4];
#pragma unroll
    for (int i = 0; i < MI; i++)
#pragma unroll
        for (int j = 0; j < NI; j++)
#pragma unroll
            for (int q = 0; q < 4; q++) acc[i][j][q] = 0.f;

    load_stage(0, 0);

    int r16 = lane % 16, c8 = (lane >> 4) * 8;
    int grp = lane >> 3;
    int bnr = (grp >> 1) * 8 + (lane & 7);
    int bkc = (grp & 1) * 8;

    for (int kt = 0; kt < KT; kt++) {
        asm volatile("cp.async.wait_group 0;");
        __syncthreads();
        if (kt + 1 < KT) load_stage(kt + 1, (kt + 1) & 1);
        int buf = kt & 1;

        uint32_t ah[MI][4], al[MI][4];
#pragma unroll
        for (int mi = 0; mi < MI; mi++) {
            int row = warp_m * (MI * 16) + mi * 16 + r16;
            uint32_t pa = (uint32_t)__cvta_generic_to_shared(&sAh[buf][swz(row, c8)]);
            LDSM4(ah[mi], pa);
            pa = (uint32_t)__cvta_generic_to_shared(&sAl[buf][swz(row, c8)]);
            LDSM4(al[mi], pa);
        }
        uint32_t bh[NI][2], bl[NI][2];
#pragma unroll
        for (int nj = 0; nj < NI / 2; nj++) {
            int n = warp_n * (NI * 8) + nj * 16 + bnr;
            uint32_t regs[4];
            uint32_t pb = (uint32_t)__cvta_generic_to_shared(&sBh[buf][swz(n, bkc)]);
            LDSM4(regs, pb);
            bh[2 * nj][0] = regs[0]; bh[2 * nj][1] = regs[1];
            bh[2 * nj + 1][0] = regs[2]; bh[2 * nj + 1][1] = regs[3];
            pb = (uint32_t)__cvta_generic_to_shared(&sBl[buf][swz(n, bkc)]);
            LDSM4(regs, pb);
            bl[2 * nj][0] = regs[0]; bl[2 * nj][1] = regs[1];
            bl[2 * nj + 1][0] = regs[2]; bl[2 * nj + 1][1] = regs[3];
        }
#pragma unroll
        for (int mi = 0; mi < MI; mi++)
#pragma unroll
            for (int ni = 0; ni < NI; ni++) {
                MMA_B16(acc[mi][ni], ah[mi], bh[ni]);
                MMA_B16(acc[mi][ni], ah[mi], bl[ni]);
                MMA_B16(acc[mi][ni], al[mi], bh[ni]);
            }
    }

#pragma unroll
    for (int mi = 0; mi < MI; mi++) {
        int row = m0 + warp_m * (MI * 16) + mi * 16 + (lane >> 2);
#pragma unroll
        for (int ni = 0; ni < NI; ni++) {
            int col = n0 + warp_n * (NI * 8) + ni * 8 + (lane & 3) * 2;
            if (col < N) {
                float* p = C + (size_t)row * N + col;
                p[0] = acc[mi][ni][0]; p[1] = acc[mi][ni][1];
                float* q = C + (size_t)(row + 8) * N + col;
                q[0] = acc[mi][ni][2]; q[1] = acc[mi][ni][3];
            }
        }
    }
}

// ---------------- causal depthwise conv (DC=4) + silu ----------------------
__global__ void dwconv(const float* __restrict__ cw, const float* __restrict__ cb) {
    int idx = blockIdx.x * blockDim.x + threadIdx.x;
    int d = idx & (DI - 1);
    int m = idx >> 9;
    int t = m & (T - 1);
    float acc = cb[d];
#pragma unroll
    for (int j = 0; j < DC; j++) {
        int tt = t + j - (DC - 1);
        if (tt >= 0)
            acc += g_xz[(size_t)(m + j - (DC - 1)) * (2 * DI) + d] * cw[d * DC + j];
    }
    float s = acc / (1.f + __expf(-acc));
    size_t o = (size_t)m * DI + d;
    g_xc[o] = s;
    split2(s, g_xch[o], g_xcl[o]);
}

// ---------------- dt proj + softplus + packing -----------------------------
__global__ void dt_pack(const float* __restrict__ dtw, const float* __restrict__ dtb,
                        const float* __restrict__ Dp) {
    int m = blockIdx.x;
    int d = threadIdx.x;
    __shared__ float sdtr[DR];
    if (d < DR) sdtr[d] = g_dbl[(size_t)m * DBLW + d];
    __syncthreads();
    float acc = dtb[d];
    const float4* w = (const float4*)(dtw + d * DR);
#pragma unroll
    for (int r4 = 0; r4 < 4; r4++) {
        float4 wv = w[r4];
        acc += sdtr[r4 * 4 + 0] * wv.x + sdtr[r4 * 4 + 1] * wv.y +
               sdtr[r4 * 4 + 2] * wv.z + sdtr[r4 * 4 + 3] * wv.w;
    }
    float dt = fmaxf(acc, 0.f) + log1pf(__expf(-fabsf(acc)));
    float xc = g_xc[(size_t)m * DI + d];
    float z = g_xz[(size_t)m * 2 * DI + DI + d];
    float sz = z / (1.f + __expf(-z));
    g_P[(size_t)m * DI + d] = make_float4(dt, dt * xc, Dp[d] * xc, sz);
}

// ---------------- selective scan --------------------------------------------
__global__ void __launch_bounds__(128) scan_kernel(const float* __restrict__ A_log) {
    int b = blockIdx.y;
    int sp = threadIdx.x & 3;
    int d = blockIdx.x * 32 + (threadIdx.x >> 2);
    float An[4], h[4] = {0.f, 0.f, 0.f, 0.f};
#pragma unroll
    for (int i = 0; i < 4; i++) An[i] = -__expf(A_log[d * DS + sp * 4 + i]);
    const float4* Pp = &g_P[(size_t)b * T * DI + d];
    const float* dblb = g_dbl + (size_t)b * T * DBLW;
    size_t ybase = (size_t)b * T * DI + d;
    for (int t = 0; t < T; t++) {
        float4 p = Pp[(size_t)t * DI];
        float4 Bv = *(const float4*)(dblb + (size_t)t * DBLW + DR + sp * 4);
        float4 Cv = *(const float4*)(dblb + (size_t)t * DBLW + DR + DS + sp * 4);
        float y;
        h[0] = h[0] * __expf(p.x * An[0]) + p.y * Bv.x;  y  = h[0] * Cv.x;
        h[1] = h[1] * __expf(p.x * An[1]) + p.y * Bv.y;  y += h[1] * Cv.y;
        h[2] = h[2] * __expf(p.x * An[2]) + p.y * Bv.z;  y += h[2] * Cv.z;
        h[3] = h[3] * __expf(p.x * An[3]) + p.y * Bv.w;  y += h[3] * Cv.w;
        y += __shfl_xor_sync(0xffffffffu, y, 1);
        y += __shfl_xor_sync(0xffffffffu, y, 2);
        if (sp == 0) {
            float yv = (y + p.z) * p.w;
            size_t o = ybase + (size_t)t * DI;
            split2(yv, g_yh[o], g_yl[o]);
        }
    }
}

// ---------------- residual add + layernorm ---------------------------------
__global__ void resid_ln(const float* __restrict__ g, const float* __restrict__ bb) {
    int m = blockIdx.x;
    int hh = threadIdx.x;
    float v = g_h[(size_t)m * H + hh] + g_out[(size_t)m * H + hh];
    __shared__ float red[8];
    __shared__ float smean, srstd;
    float s = v;
#pragma unroll
    for (int o = 16; o > 0; o >>= 1) s += __shfl_xor_sync(~0u, s, o);
    if ((hh & 31) == 0) red[hh >> 5] = s;
    __syncthreads();
    if (hh == 0) {
        float tot = 0;
#pragma unroll
        for (int i = 0; i < 8; i++) tot += red[i];
        smean = tot * (1.f / H);
    }
    __syncthreads();
    float dv = v - smean;
    float q = dv * dv;
#pragma unroll
    for (int o = 16; o > 0; o >>= 1) q += __shfl_xor_sync(~0u, q, o);
    if ((hh & 31) == 0) red[hh >> 5] = q;
    __syncthreads();
    if (hh == 0) {
        float tot = 0;
#pragma unroll
        for (int i = 0; i < 8; i++) tot += red[i];
        srstd = rsqrtf(tot * (1.f / H) + 1e-5f);
    }
    __syncthreads();
    float o = dv * srstd * g[hh] + bb[hh];
    size_t idx = (size_t)m * H + hh;
    g_h[idx] = o;
    split2(o, g_hh[idx], g_hl[idx]);
}

// ---------------- mean over T + final proj ----------------------------------
__global__ void mean_part() {
    int b = blockIdx.y;
    int chunk = blockIdx.x;
    int hh = threadIdx.x;
    float acc = 0.f;
    for (int tt = 0; tt < 128; tt++) {
        int t = chunk * 128 + tt;
        acc += g_h[((size_t)(b * T + t)) * H + hh];
    }
    g_part[(size_t)chunk * Bb * H + b * H + hh] = acc;
}

__global__ void mean_comb() {
    int i = blockIdx.x * blockDim.x + threadIdx.x;
    if (i >= Bb * H) return;
    float a = 0.f;
#pragma unroll
    for (int c = 0; c < 16; c++) a += g_part[(size_t)c * Bb * H + i];
    g_hmean[i] = a * (1.f / T);
}

__global__ void final_proj(const float* __restrict__ ow, const float* __restrict__ ob,
                           float* __restrict__ out) {
    int i = threadIdx.x;
    if (i >= Bb * OUTD) return;
    int b = i / OUTD, o = i % OUTD;
    float acc = 0.f;
    for (int hh = 0; hh < H; hh++) acc += g_hmean[b * H + hh] * ow[o * H + hh];
    out[b * OUTD + o] = acc + ob[o];
}

// ---------------- launch -----------------------------------------------------
extern "C" void kernel_launch(void* const* d_in, const int* in_sizes, int n_in,
                              void* d_out, int out_size) {
    const float* x     = (const float*)d_in[0];
    const float* w3    = (const float*)d_in[1];
    const float* b3    = (const float*)d_in[2];
    const float* w5    = (const float*)d_in[3];
    const float* b5    = (const float*)d_in[4];
    const float* w7    = (const float*)d_in[5];
    const float* b7    = (const float*)d_in[6];
    const float* ipw   = (const float*)d_in[7];
    const float* cw    = (const float*)d_in[8];
    const float* cb    = (const float*)d_in[9];
    const float* xpw   = (const float*)d_in[10];
    const float* dtw   = (const float*)d_in[11];
    const float* dtb   = (const float*)d_in[12];
    const float* A_log = (const float*)d_in[13];
    const float* Dp    = (const float*)d_in[14];
    const float* opw   = (const float*)d_in[15];
    const float* ln_g  = (const float*)d_in[16];
    const float* ln_b  = (const float*)d_in[17];
    const float* ow    = (const float*)d_in[18];
    const float* ob    = (const float*)d_in[19];

    float *pxz, *pdbl, *pout;
    __nv_bfloat16 *phh, *phl, *pxch, *pxcl, *pyh, *pyl;
    __nv_bfloat16 *pipwh, *pipwl, *pxpwh, *pxpwl, *popwh, *popwl;
    cudaGetSymbolAddress((void**)&pxz,   g_xz);
    cudaGetSymbolAddress((void**)&pdbl,  g_dbl);
    cudaGetSymbolAddress((void**)&pout,  g_out);
    cudaGetSymbolAddress((void**)&phh,   g_hh);
    cudaGetSymbolAddress((void**)&phl,   g_hl);
    cudaGetSymbolAddress((void**)&pxch,  g_xch);
    cudaGetSymbolAddress((void**)&pxcl,  g_xcl);
    cudaGetSymbolAddress((void**)&pyh,   g_yh);
    cudaGetSymbolAddress((void**)&pyl,   g_yl);
    cudaGetSymbolAddress((void**)&pipwh, g_ipw_h);
    cudaGetSymbolAddress((void**)&pipwl, g_ipw_l);
    cudaGetSymbolAddress((void**)&pxpwh, g_xpw_h);
    cudaGetSymbolAddress((void**)&pxpwl, g_xpw_l);
    cudaGetSymbolAddress((void**)&popwh, g_opw_h);
    cudaGetSymbolAddress((void**)&popwl, g_opw_l);

    // weight conversions
    cvt_split<<<(DEPTH * 2 * DI * H + 255) / 256, 256>>>(ipw, pipwh, pipwl, DEPTH * 2 * DI * H);
    cvt_split<<<(DEPTH * H * DI + 255) / 256, 256>>>(opw, popwh, popwl, DEPTH * H * DI);
    cvt_xpw<<<(DEPTH * XPW_PAD * DI + 255) / 256, 256>>>(xpw);

    prep_front<<<(H * Cc * 7 + 255) / 256, 256>>>(w3, w5, w7);
    front_conv<<<M_TOT, 256>>>(x, b3, b5, b7);

    for (int l = 0; l < DEPTH; l++) {
        // in_proj: [M,1024] = h[M,256] x ipw^T
        mma_gemm<128><<<dim3((2 * DI) / 128, M_TOT / 128), 256>>>(
            phh, phl, pipwh + (size_t)l * 2 * DI * H, pipwl + (size_t)l * 2 * DI * H,
            pxz, 2 * DI, H);
        dwconv<<<(M_TOT * DI) / 256, 256>>>(cw + (size_t)l * DI * DC, cb + (size_t)l * DI);
        // x_proj: [M,48] = xc[M,512] x xpw^T (padded to 64 rows)
        mma_gemm<64><<<dim3(1, M_TOT / 128), 256>>>(
            pxch, pxcl, pxpwh + (size_t)l * XPW_PAD * DI, pxpwl + (size_t)l * XPW_PAD * DI,
            pdbl, DBLW, DI);
        dt_pack<<<M_TOT, DI>>>(dtw + (size_t)l * DI * DR, dtb + (size_t)l * DI,
                               Dp + (size_t)l * DI);
        scan_kernel<<<dim3(DI / 32, Bb), 128>>>(A_log + (size_t)l * DI * DS);
        // out_proj: [M,256] = y[M,512] x opw^T
        mma_gemm<128><<<dim3(H / 128, M_TOT / 128), 256>>>(
            pyh, pyl, popwh + (size_t)l * H * DI, popwl + (size_t)l * H * DI,
            pout, H, DI);
        resid_ln<<<M_TOT, H>>>(ln_g, ln_b);
    }

    mean_part<<<dim3(T / 128, Bb), H>>>();
    mean_comb<<<(Bb * H + 255) / 256, 256>>>();
    final_proj<<<1, 256>>>(ow, ob, (float*)d_out);
}